// round 14
// baseline (speedup 1.0000x reference)
#include <cuda_runtime.h>
#include <cuda_bf16.h>
#include <cstdint>
#include <math.h>

#define L      65536
#define IMG    256
#define BATCH  2
#define DIMC   128
#define HEADS  8
#define CH     16

// ---- scratch (device globals; no allocation allowed) ----
__device__ float g_qkv[(size_t)BATCH * 384 * L];   // pointwise qkv output
__device__ float g_v  [(size_t)BATCH * DIMC * L];  // depthwise v
__device__ float g_S  [BATCH * HEADS * CH * CH];   // q·k^T Gram
__device__ float g_nq [BATCH * HEADS * CH];        // sum q^2
__device__ float g_nk [BATCH * HEADS * CH];        // sum k^2
__device__ float g_M  [BATCH * DIMC * DIMC];       // proj @ blockdiag(attn)
__device__ float g_attnF[BATCH * HEADS * CH * CH]; // final per-head attn

// pre-split weights (bf16 hi/lo)
__device__ __nv_bfloat16 g_Whi[384 * DIMC], g_Wlo[384 * DIMC];
__device__ __nv_bfloat16 g_Mhi[BATCH * DIMC * DIMC], g_Mlo[BATCH * DIMC * DIMC];

// ================= mma.sync helpers (sm_80+ PTX, valid on compute_103) ======
__device__ __forceinline__ uint32_t smem_u32(const void* p) {
    uint32_t a;
    asm("{ .reg .u64 t; cvta.to.shared.u64 t, %1; cvt.u32.u64 %0, t; }"
        : "=r"(a) : "l"(p));
    return a;
}
__device__ __forceinline__ void ldsm_x4(uint32_t* r, uint32_t addr) {
    asm volatile("ldmatrix.sync.aligned.m8n8.x4.shared.b16 {%0,%1,%2,%3}, [%4];"
                 : "=r"(r[0]), "=r"(r[1]), "=r"(r[2]), "=r"(r[3]) : "r"(addr));
}
__device__ __forceinline__ void ldsm_x4_t(uint32_t* r, uint32_t addr) {
    asm volatile("ldmatrix.sync.aligned.m8n8.x4.trans.shared.b16 {%0,%1,%2,%3}, [%4];"
                 : "=r"(r[0]), "=r"(r[1]), "=r"(r[2]), "=r"(r[3]) : "r"(addr));
}
__device__ __forceinline__ void mma_bf16(float* c, const uint32_t* a,
                                         uint32_t b0, uint32_t b1) {
    asm volatile(
        "mma.sync.aligned.m16n8k16.row.col.f32.bf16.bf16.f32 "
        "{%0,%1,%2,%3}, {%4,%5,%6,%7}, {%8,%9}, {%0,%1,%2,%3};"
        : "+f"(c[0]), "+f"(c[1]), "+f"(c[2]), "+f"(c[3])
        : "r"(a[0]), "r"(a[1]), "r"(a[2]), "r"(a[3]), "r"(b0), "r"(b1));
}

// fast fp32 -> bf16 hi/lo split for a pair (first elem in low 16 bits)
__device__ __forceinline__ void split_pack2(float a, float b,
                                            uint32_t& hi, uint32_t& lo) {
    __nv_bfloat162 h2 = __floats2bfloat162_rn(a, b);
    hi = *reinterpret_cast<uint32_t*>(&h2);
    float ha = __uint_as_float(hi << 16);
    float hb = __uint_as_float(hi & 0xFFFF0000u);
    __nv_bfloat162 l2 = __floats2bfloat162_rn(a - ha, b - hb);
    lo = *reinterpret_cast<uint32_t*>(&l2);
}

// smem layout (bf16 element offsets)
#define PITCH_A   136
#define PITCH_B   72
#define OFF_A_HI  0
#define OFF_A_LO  (128 * PITCH_A)
#define OFF_B_HI  (2 * 128 * PITCH_A)
#define OFF_B_LO  (2 * 128 * PITCH_A + 128 * PITCH_B)
#define SM_ELEMS  (2 * 128 * PITCH_A + 2 * 128 * PITCH_B)
#define SM_BYTES  (SM_ELEMS * 2)          // 106496 bytes -> 2 CTAs/SM

#define TILES 2

// ------------------------------------------------------------------
// Weight pre-split: f32 -> bf16 hi + lo
__global__ void split_w(const float* __restrict__ src,
                        __nv_bfloat16* __restrict__ hi,
                        __nv_bfloat16* __restrict__ lo, int n)
{
    int i = blockIdx.x * blockDim.x + threadIdx.x;
    if (i < n) {
        float v = src[i];
        __nv_bfloat16 h = __float2bfloat16(v);
        hi[i] = h;
        lo[i] = __float2bfloat16(v - __bfloat162float(h));
    }
}

// ------------------------------------------------------------------
// Tensor-core GEMM (bf16 3-split via mma.sync), pre-split A.
// o-loop inside CTA: B tile converted once, X read ONCE for all OC chunks.
// grid: (L/(64*TILES), 1, BATCH), block 256, smem SM_BYTES, 2 CTAs/SM.
__global__ __launch_bounds__(256, 2) void tc_gemm(
    const __nv_bfloat16* __restrict__ Ahi,
    const __nv_bfloat16* __restrict__ Alo, size_t a_bs, int n_ob,
    const float* __restrict__ X, size_t x_bs,
    float* __restrict__ Y, size_t y_bs)
{
    extern __shared__ __nv_bfloat16 smem[];
    const uint32_t sb = smem_u32(smem);

    const int t = threadIdx.x;
    const int bz = blockIdx.z;
    const int p_base = blockIdx.x * (64 * TILES);

    const float* Xb = X + (size_t)bz * x_bs;
    float*       Yb = Y + (size_t)bz * y_bs;

    const int lane = t & 31, wid = t >> 5;
    const int wo = wid >> 2, wp = wid & 3;
    const int lr = lane & 7, sel = lane >> 3;

    const uint32_t aoff = (uint32_t)(wo * 64 + (sel & 1) * 8 + lr) * PITCH_A +
                          (sel >> 1) * 8;
    const uint32_t boff = (uint32_t)((sel & 1) * 8 + lr) * PITCH_B +
                          wp * 16 + (sel >> 1) * 8;
    const int gID = lane >> 2, q4 = lane & 3;

    const int j  = t & 31;
    const int kr = t >> 5;

    // A-copy indices (hoisted)
    const int ao_row = t >> 1;
    const int ao_kh  = (t & 1) * 64;
    uint4* dh = (uint4*)(smem + OFF_A_HI + ao_row * PITCH_A + ao_kh);
    uint4* dl = (uint4*)(smem + OFF_A_LO + ao_row * PITCH_A + ao_kh);

    for (int tile = 0; tile < TILES; tile++) {
        const int p0 = p_base + tile * 64;

        // ---- B tile: 128 k x 64 p, f32 -> bf16 hi/lo, [k][p] pitch 72 ----
        {
            const float* xg = Xb + p0 + j * 2;
#pragma unroll
            for (int i = 0; i < 16; i++) {
                const int k = kr + i * 8;
                float2 v = *(const float2*)(xg + (size_t)k * L);
                uint32_t hi, lo;
                split_pack2(v.x, v.y, hi, lo);
                ((uint32_t*)(smem + OFF_B_HI + k * PITCH_B))[j] = hi;
                ((uint32_t*)(smem + OFF_B_LO + k * PITCH_B))[j] = lo;
            }
        }

        for (int ob = 0; ob < n_ob; ob++) {
            const int o0 = ob * 128;
            // ---- A chunk: copy pre-split bf16 (128 o x 128 k), L2-resident ----
            {
                const size_t goff = (size_t)bz * a_bs +
                                    (size_t)(o0 + ao_row) * 128 + ao_kh;
                const uint4* sh = (const uint4*)(Ahi + goff);
                const uint4* sl = (const uint4*)(Alo + goff);
#pragma unroll
                for (int i = 0; i < 8; i++) { dh[i] = sh[i]; dl[i] = sl[i]; }
            }
            __syncthreads();   // A (+ B on first ob) visible to all warps

            float acc[4][2][4];
#pragma unroll
            for (int mi = 0; mi < 4; mi++)
#pragma unroll
                for (int ni = 0; ni < 2; ni++)
#pragma unroll
                    for (int jj = 0; jj < 4; jj++) acc[mi][ni][jj] = 0.f;

#pragma unroll
            for (int k0 = 0; k0 < 128; k0 += 16) {
                uint32_t ahi[4][4], alo[4][4], bhi[4], blo[4];
                const uint32_t aAddr = sb + (aoff + k0) * 2;
#pragma unroll
                for (int mi = 0; mi < 4; mi++)
                    ldsm_x4(ahi[mi], aAddr + (OFF_A_HI + mi * 16 * PITCH_A) * 2);
#pragma unroll
                for (int mi = 0; mi < 4; mi++)
                    ldsm_x4(alo[mi], aAddr + (OFF_A_LO + mi * 16 * PITCH_A) * 2);
                const uint32_t bAddr = sb + (boff + (uint32_t)k0 * PITCH_B) * 2;
                ldsm_x4_t(bhi, bAddr + OFF_B_HI * 2);
                ldsm_x4_t(blo, bAddr + OFF_B_LO * 2);

#pragma unroll
                for (int mi = 0; mi < 4; mi++) {
                    mma_bf16(acc[mi][0], ahi[mi], bhi[0], bhi[1]);
                    mma_bf16(acc[mi][1], ahi[mi], bhi[2], bhi[3]);
                    mma_bf16(acc[mi][0], ahi[mi], blo[0], blo[1]);
                    mma_bf16(acc[mi][1], ahi[mi], blo[2], blo[3]);
                    mma_bf16(acc[mi][0], alo[mi], bhi[0], bhi[1]);
                    mma_bf16(acc[mi][1], alo[mi], bhi[2], bhi[3]);
                }
            }

#pragma unroll
            for (int mi = 0; mi < 4; mi++) {
                const int o = o0 + wo * 64 + mi * 16 + gID;
#pragma unroll
                for (int ni = 0; ni < 2; ni++) {
                    const int p = p0 + wp * 16 + ni * 8 + q4 * 2;
                    *(float2*)(Yb + (size_t)o * L + p) =
                        make_float2(acc[mi][ni][0], acc[mi][ni][1]);
                    *(float2*)(Yb + (size_t)(o + 8) * L + p) =
                        make_float2(acc[mi][ni][2], acc[mi][ni][3]);
                }
            }
            __syncthreads();   // all reads of A/B done before rewrite
        }
    }
}

// ------------------------------------------------------------------
__global__ void zero_acc() {
    int t = blockIdx.x * blockDim.x + threadIdx.x;
    if (t < BATCH * HEADS * CH * CH) g_S[t] = 0.f;
    if (t < BATCH * HEADS * CH) { g_nq[t] = 0.f; g_nk[t] = 0.f; }
}

// ------------------------------------------------------------------
// Depthwise 3x3 on q & k channels of one head + Gram/norm reduction.
// Gram/norm phases vectorized (float4, pitch 260 -> <=2-way conflicts).
__global__ __launch_bounds__(256) void dw_qk_gram(const float* __restrict__ dww)
{
    __shared__ __align__(16) float s_in[32 * 340];
    __shared__ float w_s[32 * 9];

    const int z = blockIdx.z;
    const int b = z >> 3, h = z & 7;
    const int x0 = blockIdx.x * 32, y0 = blockIdx.y * 8;
    const int t = threadIdx.x;

    for (int i = t; i < 32 * 9; i += 256) {
        int lc = i / 9, jj = i % 9;
        int gch = (lc < 16) ? (h * 16 + lc) : (128 + h * 16 + (lc - 16));
        w_s[i] = dww[gch * 9 + jj];
    }

    // hoisted halo coordinates (computed once)
    const int r0_ = t / 34,          c0_ = t - r0_ * 34;
    const int y0g = y0 + r0_ - 1,    x0g = x0 + c0_ - 1;
    const bool v0 = ((unsigned)y0g < IMG) & ((unsigned)x0g < IMG);
    const size_t off0 = (size_t)y0g * IMG + x0g;

    const float* srcq = g_qkv + ((size_t)b * 384 + h * 16) * L;
    const float* srck = g_qkv + ((size_t)b * 384 + 128 + h * 16) * L;

    // main region: branch-free, loads batch together
#pragma unroll
    for (int c = 0; c < 16; c++) {
        s_in[c * 340 + t]        = v0 ? srcq[(size_t)c * L + off0] : 0.f;
        s_in[(16 + c) * 340 + t] = v0 ? srck[(size_t)c * L + off0] : 0.f;
    }
    // tail region: single branch wrapping all tail loads
    if (t < 84) {
        const int i1  = t + 256;
        const int r1_ = i1 / 34, c1_ = i1 - r1_ * 34;
        const int y1g = y0 + r1_ - 1, x1g = x0 + c1_ - 1;
        const bool v1 = ((unsigned)y1g < IMG) & ((unsigned)x1g < IMG);
        const size_t off1 = (size_t)y1g * IMG + x1g;
#pragma unroll
        for (int c = 0; c < 16; c++) {
            s_in[c * 340 + 256 + t]        = v1 ? srcq[(size_t)c * L + off1] : 0.f;
            s_in[(16 + c) * 340 + 256 + t] = v1 ? srck[(size_t)c * L + off1] : 0.f;
        }
    }
    __syncthreads();

    const int tx = t & 31, ty = t >> 5;
    float q_r[16], k_r[16];
#pragma unroll
    for (int c = 0; c < 16; c++) {
        const float* bq = &s_in[c * 340 + ty * 34 + tx];
        const float* wq = &w_s[c * 9];
        const float* bk = &s_in[(16 + c) * 340 + ty * 34 + tx];
        const float* wk = &w_s[(16 + c) * 9];
        float aq = 0.f, ak = 0.f;
#pragma unroll
        for (int dy = 0; dy < 3; dy++)
#pragma unroll
            for (int dx = 0; dx < 3; dx++) {
                aq += wq[dy * 3 + dx] * bq[dy * 34 + dx];
                ak += wk[dy * 3 + dx] * bk[dy * 34 + dx];
            }
        q_r[c] = aq; k_r[c] = ak;
    }
    __syncthreads();

    // transpose buffers: pitch 260 floats (65 float4s -> 2-way worst conflicts)
    float* q_s = s_in;
    float* k_s = s_in + 16 * 260;
#pragma unroll
    for (int c = 0; c < 16; c++) {
        q_s[c * 260 + t] = q_r[c];
        k_s[c * 260 + t] = k_r[c];
    }
    __syncthreads();

    {
        int c = t >> 4, d = t & 15;
        const float4* q4 = (const float4*)(q_s + c * 260);
        const float4* k4 = (const float4*)(k_s + d * 260);
        float s = 0.f;
#pragma unroll 8
        for (int i = 0; i < 64; i++) {
            float4 a = q4[i], bb = k4[i];
            s += a.x * bb.x + a.y * bb.y + a.z * bb.z + a.w * bb.w;
        }
        atomicAdd(&g_S[(z * 16 + c) * 16 + d], s);
    }
    if (t < 16) {
        const float4* q4 = (const float4*)(q_s + t * 260);
        float s = 0.f;
#pragma unroll 8
        for (int i = 0; i < 64; i++) {
            float4 a = q4[i];
            s += a.x * a.x + a.y * a.y + a.z * a.z + a.w * a.w;
        }
        atomicAdd(&g_nq[z * 16 + t], s);
    } else if (t < 32) {
        const float4* k4 = (const float4*)(k_s + (t - 16) * 260);
        float s = 0.f;
#pragma unroll 8
        for (int i = 0; i < 64; i++) {
            float4 a = k4[i];
            s += a.x * a.x + a.y * a.y + a.z * a.z + a.w * a.w;
        }
        atomicAdd(&g_nk[z * 16 + t - 16], s);
    }
}

// ------------------------------------------------------------------
// Depthwise 3x3 on v channels (hoisted coords, branch-free main + one tail).
__global__ __launch_bounds__(256) void dw_v(const float* __restrict__ dww)
{
    __shared__ float s_in[16 * 340];
    __shared__ float w_s[16 * 9];

    const int z = blockIdx.z;
    const int b = z >> 3, h = z & 7;
    const int x0 = blockIdx.x * 32, y0 = blockIdx.y * 8;
    const int t = threadIdx.x;

    for (int i = t; i < 16 * 9; i += 256)
        w_s[i] = dww[(256 + h * 16) * 9 + i];

    const int r0_ = t / 34,          c0_ = t - r0_ * 34;
    const int y0g = y0 + r0_ - 1,    x0g = x0 + c0_ - 1;
    const bool v0 = ((unsigned)y0g < IMG) & ((unsigned)x0g < IMG);
    const size_t off0 = (size_t)y0g * IMG + x0g;

    const float* src = g_qkv + ((size_t)b * 384 + 256 + h * 16) * L;
#pragma unroll
    for (int c = 0; c < 16; c++)
        s_in[c * 340 + t] = v0 ? src[(size_t)c * L + off0] : 0.f;
    if (t < 84) {
        const int i1  = t + 256;
        const int r1_ = i1 / 34, c1_ = i1 - r1_ * 34;
        const int y1g = y0 + r1_ - 1, x1g = x0 + c1_ - 1;
        const bool v1 = ((unsigned)y1g < IMG) & ((unsigned)x1g < IMG);
        const size_t off1 = (size_t)y1g * IMG + x1g;
#pragma unroll
        for (int c = 0; c < 16; c++)
            s_in[c * 340 + 256 + t] = v1 ? src[(size_t)c * L + off1] : 0.f;
    }
    __syncthreads();

    const int tx = t & 31, ty = t >> 5;
    const int p = (y0 + ty) * IMG + x0 + tx;
    float* dst = g_v + ((size_t)b * DIMC + h * 16) * L;
#pragma unroll
    for (int lc = 0; lc < 16; lc++) {
        const float* base = &s_in[lc * 340 + ty * 34 + tx];
        const float* w = &w_s[lc * 9];
        float acc = 0.f;
#pragma unroll
        for (int dy = 0; dy < 3; dy++)
#pragma unroll
            for (int dx = 0; dx < 3; dx++)
                acc += w[dy * 3 + dx] * base[dy * 34 + dx];
        dst[(size_t)lc * L + p] = acc;
    }
}

// ------------------------------------------------------------------
// Attention math only (256 threads = one per (b,h,c) row).
__global__ void attn_small(const float* __restrict__ attca_w,
                           const float* __restrict__ temperature)
{
    const int t = threadIdx.x;
    int bh = t >> 4;
    int c  = t & 15;
    int h  = bh & 7;
    float dq = fmaxf(sqrtf(g_nq[bh * 16 + c]), 1e-12f);
    float temp = temperature[h];
    float row[16];
#pragma unroll
    for (int d = 0; d < 16; d++) {
        float dk = fmaxf(sqrtf(g_nk[bh * 16 + d]), 1e-12f);
        row[d] = g_S[(bh * 16 + c) * 16 + d] / (dq * dk) * temp;
    }
    float m = row[0];
#pragma unroll
    for (int d = 1; d < 16; d++) m = fmaxf(m, row[d]);
    float ex[16], sum = 0.f;
#pragma unroll
    for (int d = 0; d < 16; d++) { ex[d] = expf(row[d] - m); sum += ex[d]; }
    float inv = 1.f / sum;
    float a1[16];
#pragma unroll
    for (int d = 0; d < 16; d++) {
        float r = fmaxf(row[d], 0.f);
        float a = r * r;
        float g = a * 0.5f * (1.f + erff(a * 0.7071067811865476f));
        a1[d] = g * a;
    }
#pragma unroll
    for (int d = 0; d < 16; d++) {
        float sc = 0.f, sh = 0.f;
#pragma unroll
        for (int e = 0; e < 16; e++) {
            sc += attca_w[d * 16 + e] * a1[e];
            sh += attca_w[(16 + d) * 16 + e] * a1[e];
        }
        g_attnF[(bh * 16 + c) * 16 + d] = ex[d] * inv * (1.f + sc) + sh;
    }
}

// ------------------------------------------------------------------
// M[b][o][h*16+d] = sum_c proj_w[o][h*16+c] * attnF[b,h,c][d]
__global__ void proj_fold(const float* __restrict__ proj_w)
{
    int e  = blockIdx.x * 256 + threadIdx.x;   // 0..32767
    int b2 = e >> 14;
    int o  = (e >> 7) & 127;
    int jj = e & 127;
    int h2 = jj >> 4, d = jj & 15;
    float s = 0.f;
#pragma unroll
    for (int c2 = 0; c2 < 16; c2++)
        s += proj_w[o * 128 + h2 * 16 + c2] *
             g_attnF[((b2 * 8 + h2) * 16 + c2) * 16 + d];
    g_M[e] = s;
}

// ------------------------------------------------------------------
extern "C" void kernel_launch(void* const* d_in, const int* in_sizes, int n_in,
                              void* d_out, int out_size)
{
    const float* x           = (const float*)d_in[0];
    const float* qkv_w       = (const float*)d_in[1];
    const float* dw_w        = (const float*)d_in[2];
    const float* proj_w      = (const float*)d_in[3];
    const float* attca_w     = (const float*)d_in[4];
    const float* temperature = (const float*)d_in[5];
    float* out = (float*)d_out;

    float *p_qkv, *p_v, *p_M;
    __nv_bfloat16 *p_Whi, *p_Wlo, *p_Mhi, *p_Mlo;
    cudaGetSymbolAddress((void**)&p_qkv, g_qkv);
    cudaGetSymbolAddress((void**)&p_v,   g_v);
    cudaGetSymbolAddress((void**)&p_M,   g_M);
    cudaGetSymbolAddress((void**)&p_Whi, g_Whi);
    cudaGetSymbolAddress((void**)&p_Wlo, g_Wlo);
    cudaGetSymbolAddress((void**)&p_Mhi, g_Mhi);
    cudaGetSymbolAddress((void**)&p_Mlo, g_Mlo);

    cudaFuncSetAttribute(tc_gemm, cudaFuncAttributeMaxDynamicSharedMemorySize,
                         SM_BYTES);

    zero_acc<<<16, 256>>>();
    split_w<<<(384 * DIMC + 255) / 256, 256>>>(qkv_w, p_Whi, p_Wlo, 384 * DIMC);
    // qkv pointwise: [384x128] @ x[b][128][L] — X read once, 3 o-chunks inside
    tc_gemm<<<dim3(L / (64 * TILES), 1, BATCH), 256, SM_BYTES>>>(
        p_Whi, p_Wlo, 0, 3, x, (size_t)DIMC * L, p_qkv, (size_t)384 * L);
    // depthwise q/k + Gram reductions
    dw_qk_gram<<<dim3(IMG / 32, IMG / 8, BATCH * HEADS), 256>>>(dw_w);
    // depthwise v
    dw_v<<<dim3(IMG / 32, IMG / 8, BATCH * HEADS), 256>>>(dw_w);
    // attention math, then fold proj into M (parallel), then split M
    attn_small<<<1, 256>>>(attca_w, temperature);
    proj_fold<<<128, 256>>>(proj_w);
    split_w<<<(BATCH * DIMC * DIMC + 255) / 256, 256>>>(
        p_M, p_Mhi, p_Mlo, BATCH * DIMC * DIMC);
    // out = M_b @ v
    tc_gemm<<<dim3(L / (64 * TILES), 1, BATCH), 256, SM_BYTES>>>(
        p_Mhi, p_Mlo, (size_t)DIMC * DIMC, 1, p_v, (size_t)DIMC * L,
        out, (size_t)DIMC * L);
}

// round 15
// speedup vs baseline: 1.2260x; 1.2260x over previous
#include <cuda_runtime.h>
#include <cuda_bf16.h>
#include <cstdint>
#include <math.h>

#define L      65536
#define IMG    256
#define BATCH  2
#define DIMC   128
#define HEADS  8
#define CH     16

// ---- scratch (device globals; no allocation allowed) ----
__device__ float g_qkv[(size_t)BATCH * 384 * L];   // pointwise qkv output
__device__ float g_v  [(size_t)BATCH * DIMC * L];  // depthwise v
__device__ float g_S  [BATCH * HEADS * CH * CH];   // q·k^T Gram
__device__ float g_nq [BATCH * HEADS * CH];        // sum q^2
__device__ float g_nk [BATCH * HEADS * CH];        // sum k^2
__device__ float g_M  [BATCH * DIMC * DIMC];       // proj @ blockdiag(attn)
__device__ float g_attnF[BATCH * HEADS * CH * CH]; // final per-head attn

// pre-split weights (bf16 hi/lo)
__device__ __nv_bfloat16 g_Whi[384 * DIMC], g_Wlo[384 * DIMC];
__device__ __nv_bfloat16 g_Mhi[BATCH * DIMC * DIMC], g_Mlo[BATCH * DIMC * DIMC];

// ================= mma.sync helpers (sm_80+ PTX, valid on compute_103) ======
__device__ __forceinline__ uint32_t smem_u32(const void* p) {
    uint32_t a;
    asm("{ .reg .u64 t; cvta.to.shared.u64 t, %1; cvt.u32.u64 %0, t; }"
        : "=r"(a) : "l"(p));
    return a;
}
__device__ __forceinline__ void ldsm_x4(uint32_t* r, uint32_t addr) {
    asm volatile("ldmatrix.sync.aligned.m8n8.x4.shared.b16 {%0,%1,%2,%3}, [%4];"
                 : "=r"(r[0]), "=r"(r[1]), "=r"(r[2]), "=r"(r[3]) : "r"(addr));
}
__device__ __forceinline__ void ldsm_x4_t(uint32_t* r, uint32_t addr) {
    asm volatile("ldmatrix.sync.aligned.m8n8.x4.trans.shared.b16 {%0,%1,%2,%3}, [%4];"
                 : "=r"(r[0]), "=r"(r[1]), "=r"(r[2]), "=r"(r[3]) : "r"(addr));
}
__device__ __forceinline__ void mma_bf16(float* c, const uint32_t* a,
                                         uint32_t b0, uint32_t b1) {
    asm volatile(
        "mma.sync.aligned.m16n8k16.row.col.f32.bf16.bf16.f32 "
        "{%0,%1,%2,%3}, {%4,%5,%6,%7}, {%8,%9}, {%0,%1,%2,%3};"
        : "+f"(c[0]), "+f"(c[1]), "+f"(c[2]), "+f"(c[3])
        : "r"(a[0]), "r"(a[1]), "r"(a[2]), "r"(a[3]), "r"(b0), "r"(b1));
}

// fast fp32 -> bf16 hi/lo split for a pair (first elem in low 16 bits)
__device__ __forceinline__ void split_pack2(float a, float b,
                                            uint32_t& hi, uint32_t& lo) {
    __nv_bfloat162 h2 = __floats2bfloat162_rn(a, b);
    hi = *reinterpret_cast<uint32_t*>(&h2);
    float ha = __uint_as_float(hi << 16);
    float hb = __uint_as_float(hi & 0xFFFF0000u);
    __nv_bfloat162 l2 = __floats2bfloat162_rn(a - ha, b - hb);
    lo = *reinterpret_cast<uint32_t*>(&l2);
}

// smem layout (bf16 element offsets)
#define PITCH_A   136
#define PITCH_B   72
#define OFF_A_HI  0
#define OFF_A_LO  (128 * PITCH_A)
#define OFF_B_HI  (2 * 128 * PITCH_A)
#define OFF_B_LO  (2 * 128 * PITCH_A + 128 * PITCH_B)
#define SM_ELEMS  (2 * 128 * PITCH_A + 2 * 128 * PITCH_B)
#define SM_BYTES  (SM_ELEMS * 2)          // 106496 bytes -> 2 CTAs/SM

#define TILES 4

// ------------------------------------------------------------------
// Weight pre-split: f32 -> bf16 hi + lo
__global__ void split_w(const float* __restrict__ src,
                        __nv_bfloat16* __restrict__ hi,
                        __nv_bfloat16* __restrict__ lo, int n)
{
    int i = blockIdx.x * blockDim.x + threadIdx.x;
    if (i < n) {
        float v = src[i];
        __nv_bfloat16 h = __float2bfloat16(v);
        hi[i] = h;
        lo[i] = __float2bfloat16(v - __bfloat162float(h));
    }
}

// ------------------------------------------------------------------
// Tensor-core GEMM (bf16 3-split via mma.sync), pre-split A.
// R13 configuration: A loaded once per CTA, grid.y = o-chunks, TILES=4.
__global__ __launch_bounds__(256, 2) void tc_gemm(
    const __nv_bfloat16* __restrict__ Ahi,
    const __nv_bfloat16* __restrict__ Alo, size_t a_bs,
    const float* __restrict__ X, size_t x_bs,
    float* __restrict__ Y, size_t y_bs)
{
    extern __shared__ __nv_bfloat16 smem[];
    const uint32_t sb = smem_u32(smem);

    const int t = threadIdx.x;
    const int bz = blockIdx.z;
    const int o0 = blockIdx.y * 128;
    const int p_base = blockIdx.x * (64 * TILES);

    const float* Xb = X + (size_t)bz * x_bs;
    float*       Yb = Y + (size_t)bz * y_bs;

    // ---- A tile: pure copy of pre-split bf16 (128 o x 128 k), pitch 136 ----
    {
        const int o = t >> 1;
        const int kh = (t & 1) * 64;
        const size_t goff = (size_t)bz * a_bs + (size_t)(o0 + o) * 128 + kh;
        const uint4* sh = (const uint4*)(Ahi + goff);
        const uint4* sl = (const uint4*)(Alo + goff);
        uint4* dh = (uint4*)(smem + OFF_A_HI + o * PITCH_A + kh);
        uint4* dl = (uint4*)(smem + OFF_A_LO + o * PITCH_A + kh);
#pragma unroll
        for (int i = 0; i < 8; i++) { dh[i] = sh[i]; dl[i] = sl[i]; }
    }

    const int lane = t & 31, wid = t >> 5;
    const int wo = wid >> 2, wp = wid & 3;
    const int lr = lane & 7, sel = lane >> 3;

    const uint32_t aoff = (uint32_t)(wo * 64 + (sel & 1) * 8 + lr) * PITCH_A +
                          (sel >> 1) * 8;
    const uint32_t boff = (uint32_t)((sel & 1) * 8 + lr) * PITCH_B +
                          wp * 16 + (sel >> 1) * 8;
    const int gID = lane >> 2, q4 = lane & 3;

    const int j  = t & 31;
    const int kr = t >> 5;

    for (int tile = 0; tile < TILES; tile++) {
        const int p0 = p_base + tile * 64;

        // ---- B tile: 128 k x 64 p, f32 -> bf16 hi/lo, [k][p] pitch 72 ----
        {
            const float* xg = Xb + p0 + j * 2;
#pragma unroll
            for (int i = 0; i < 16; i++) {
                const int k = kr + i * 8;
                float2 v = *(const float2*)(xg + (size_t)k * L);
                uint32_t hi, lo;
                split_pack2(v.x, v.y, hi, lo);
                ((uint32_t*)(smem + OFF_B_HI + k * PITCH_B))[j] = hi;
                ((uint32_t*)(smem + OFF_B_LO + k * PITCH_B))[j] = lo;
            }
        }
        __syncthreads();

        float acc[4][2][4];
#pragma unroll
        for (int mi = 0; mi < 4; mi++)
#pragma unroll
            for (int ni = 0; ni < 2; ni++)
#pragma unroll
                for (int jj = 0; jj < 4; jj++) acc[mi][ni][jj] = 0.f;

#pragma unroll
        for (int k0 = 0; k0 < 128; k0 += 16) {
            uint32_t ahi[4][4], alo[4][4], bhi[4], blo[4];
            const uint32_t aAddr = sb + (aoff + k0) * 2;
#pragma unroll
            for (int mi = 0; mi < 4; mi++)
                ldsm_x4(ahi[mi], aAddr + (OFF_A_HI + mi * 16 * PITCH_A) * 2);
#pragma unroll
            for (int mi = 0; mi < 4; mi++)
                ldsm_x4(alo[mi], aAddr + (OFF_A_LO + mi * 16 * PITCH_A) * 2);
            const uint32_t bAddr = sb + (boff + (uint32_t)k0 * PITCH_B) * 2;
            ldsm_x4_t(bhi, bAddr + OFF_B_HI * 2);
            ldsm_x4_t(blo, bAddr + OFF_B_LO * 2);

#pragma unroll
            for (int mi = 0; mi < 4; mi++) {
                mma_bf16(acc[mi][0], ahi[mi], bhi[0], bhi[1]);
                mma_bf16(acc[mi][1], ahi[mi], bhi[2], bhi[3]);
                mma_bf16(acc[mi][0], ahi[mi], blo[0], blo[1]);
                mma_bf16(acc[mi][1], ahi[mi], blo[2], blo[3]);
                mma_bf16(acc[mi][0], alo[mi], bhi[0], bhi[1]);
                mma_bf16(acc[mi][1], alo[mi], bhi[2], bhi[3]);
            }
        }

#pragma unroll
        for (int mi = 0; mi < 4; mi++) {
            const int o = o0 + wo * 64 + mi * 16 + gID;
#pragma unroll
            for (int ni = 0; ni < 2; ni++) {
                const int p = p0 + wp * 16 + ni * 8 + q4 * 2;
                *(float2*)(Yb + (size_t)o * L + p) =
                    make_float2(acc[mi][ni][0], acc[mi][ni][1]);
                *(float2*)(Yb + (size_t)(o + 8) * L + p) =
                    make_float2(acc[mi][ni][2], acc[mi][ni][3]);
            }
        }
        __syncthreads();
    }
}

// ------------------------------------------------------------------
__global__ void zero_acc() {
    int t = blockIdx.x * blockDim.x + threadIdx.x;
    if (t < BATCH * HEADS * CH * CH) g_S[t] = 0.f;
    if (t < BATCH * HEADS * CH) { g_nq[t] = 0.f; g_nk[t] = 0.f; }
}

// ------------------------------------------------------------------
// Depthwise 3x3 on q & k channels of one head + Gram/norm reduction.
// R14 version: hoisted coords + vectorized gram (float4, pitch 260).
__global__ __launch_bounds__(256) void dw_qk_gram(const float* __restrict__ dww)
{
    __shared__ __align__(16) float s_in[32 * 340];
    __shared__ float w_s[32 * 9];

    const int z = blockIdx.z;
    const int b = z >> 3, h = z & 7;
    const int x0 = blockIdx.x * 32, y0 = blockIdx.y * 8;
    const int t = threadIdx.x;

    for (int i = t; i < 32 * 9; i += 256) {
        int lc = i / 9, jj = i % 9;
        int gch = (lc < 16) ? (h * 16 + lc) : (128 + h * 16 + (lc - 16));
        w_s[i] = dww[gch * 9 + jj];
    }

    // hoisted halo coordinates (computed once)
    const int r0_ = t / 34,          c0_ = t - r0_ * 34;
    const int y0g = y0 + r0_ - 1,    x0g = x0 + c0_ - 1;
    const bool v0 = ((unsigned)y0g < IMG) & ((unsigned)x0g < IMG);
    const size_t off0 = (size_t)y0g * IMG + x0g;

    const float* srcq = g_qkv + ((size_t)b * 384 + h * 16) * L;
    const float* srck = g_qkv + ((size_t)b * 384 + 128 + h * 16) * L;

    // main region: branch-free, loads batch together
#pragma unroll
    for (int c = 0; c < 16; c++) {
        s_in[c * 340 + t]        = v0 ? srcq[(size_t)c * L + off0] : 0.f;
        s_in[(16 + c) * 340 + t] = v0 ? srck[(size_t)c * L + off0] : 0.f;
    }
    // tail region: single branch wrapping all tail loads
    if (t < 84) {
        const int i1  = t + 256;
        const int r1_ = i1 / 34, c1_ = i1 - r1_ * 34;
        const int y1g = y0 + r1_ - 1, x1g = x0 + c1_ - 1;
        const bool v1 = ((unsigned)y1g < IMG) & ((unsigned)x1g < IMG);
        const size_t off1 = (size_t)y1g * IMG + x1g;
#pragma unroll
        for (int c = 0; c < 16; c++) {
            s_in[c * 340 + 256 + t]        = v1 ? srcq[(size_t)c * L + off1] : 0.f;
            s_in[(16 + c) * 340 + 256 + t] = v1 ? srck[(size_t)c * L + off1] : 0.f;
        }
    }
    __syncthreads();

    const int tx = t & 31, ty = t >> 5;
    float q_r[16], k_r[16];
#pragma unroll
    for (int c = 0; c < 16; c++) {
        const float* bq = &s_in[c * 340 + ty * 34 + tx];
        const float* wq = &w_s[c * 9];
        const float* bk = &s_in[(16 + c) * 340 + ty * 34 + tx];
        const float* wk = &w_s[(16 + c) * 9];
        float aq = 0.f, ak = 0.f;
#pragma unroll
        for (int dy = 0; dy < 3; dy++)
#pragma unroll
            for (int dx = 0; dx < 3; dx++) {
                aq += wq[dy * 3 + dx] * bq[dy * 34 + dx];
                ak += wk[dy * 3 + dx] * bk[dy * 34 + dx];
            }
        q_r[c] = aq; k_r[c] = ak;
    }
    __syncthreads();

    // transpose buffers: pitch 260 floats (float4-aligned, 2-way worst)
    float* q_s = s_in;
    float* k_s = s_in + 16 * 260;
#pragma unroll
    for (int c = 0; c < 16; c++) {
        q_s[c * 260 + t] = q_r[c];
        k_s[c * 260 + t] = k_r[c];
    }
    __syncthreads();

    {
        int c = t >> 4, d = t & 15;
        const float4* q4 = (const float4*)(q_s + c * 260);
        const float4* k4 = (const float4*)(k_s + d * 260);
        float s = 0.f;
#pragma unroll 8
        for (int i = 0; i < 64; i++) {
            float4 a = q4[i], bb = k4[i];
            s += a.x * bb.x + a.y * bb.y + a.z * bb.z + a.w * bb.w;
        }
        atomicAdd(&g_S[(z * 16 + c) * 16 + d], s);
    }
    if (t < 16) {
        const float4* q4 = (const float4*)(q_s + t * 260);
        float s = 0.f;
#pragma unroll 8
        for (int i = 0; i < 64; i++) {
            float4 a = q4[i];
            s += a.x * a.x + a.y * a.y + a.z * a.z + a.w * a.w;
        }
        atomicAdd(&g_nq[z * 16 + t], s);
    } else if (t < 32) {
        const float4* k4 = (const float4*)(k_s + (t - 16) * 260);
        float s = 0.f;
#pragma unroll 8
        for (int i = 0; i < 64; i++) {
            float4 a = k4[i];
            s += a.x * a.x + a.y * a.y + a.z * a.z + a.w * a.w;
        }
        atomicAdd(&g_nk[z * 16 + t - 16], s);
    }
}

// ------------------------------------------------------------------
// Depthwise 3x3 on v channels (hoisted coords, branch-free main + one tail).
__global__ __launch_bounds__(256) void dw_v(const float* __restrict__ dww)
{
    __shared__ float s_in[16 * 340];
    __shared__ float w_s[16 * 9];

    const int z = blockIdx.z;
    const int b = z >> 3, h = z & 7;
    const int x0 = blockIdx.x * 32, y0 = blockIdx.y * 8;
    const int t = threadIdx.x;

    for (int i = t; i < 16 * 9; i += 256)
        w_s[i] = dww[(256 + h * 16) * 9 + i];

    const int r0_ = t / 34,          c0_ = t - r0_ * 34;
    const int y0g = y0 + r0_ - 1,    x0g = x0 + c0_ - 1;
    const bool v0 = ((unsigned)y0g < IMG) & ((unsigned)x0g < IMG);
    const size_t off0 = (size_t)y0g * IMG + x0g;

    const float* src = g_qkv + ((size_t)b * 384 + 256 + h * 16) * L;
#pragma unroll
    for (int c = 0; c < 16; c++)
        s_in[c * 340 + t] = v0 ? src[(size_t)c * L + off0] : 0.f;
    if (t < 84) {
        const int i1  = t + 256;
        const int r1_ = i1 / 34, c1_ = i1 - r1_ * 34;
        const int y1g = y0 + r1_ - 1, x1g = x0 + c1_ - 1;
        const bool v1 = ((unsigned)y1g < IMG) & ((unsigned)x1g < IMG);
        const size_t off1 = (size_t)y1g * IMG + x1g;
#pragma unroll
        for (int c = 0; c < 16; c++)
            s_in[c * 340 + 256 + t] = v1 ? src[(size_t)c * L + off1] : 0.f;
    }
    __syncthreads();

    const int tx = t & 31, ty = t >> 5;
    const int p = (y0 + ty) * IMG + x0 + tx;
    float* dst = g_v + ((size_t)b * DIMC + h * 16) * L;
#pragma unroll
    for (int lc = 0; lc < 16; lc++) {
        const float* base = &s_in[lc * 340 + ty * 34 + tx];
        const float* w = &w_s[lc * 9];
        float acc = 0.f;
#pragma unroll
        for (int dy = 0; dy < 3; dy++)
#pragma unroll
            for (int dx = 0; dx < 3; dx++)
                acc += w[dy * 3 + dx] * base[dy * 34 + dx];
        dst[(size_t)lc * L + p] = acc;
    }
}

// ------------------------------------------------------------------
// Attention math only (256 threads = one per (b,h,c) row).
__global__ void attn_small(const float* __restrict__ attca_w,
                           const float* __restrict__ temperature)
{
    const int t = threadIdx.x;
    int bh = t >> 4;
    int c  = t & 15;
    int h  = bh & 7;
    float dq = fmaxf(sqrtf(g_nq[bh * 16 + c]), 1e-12f);
    float temp = temperature[h];
    float row[16];
#pragma unroll
    for (int d = 0; d < 16; d++) {
        float dk = fmaxf(sqrtf(g_nk[bh * 16 + d]), 1e-12f);
        row[d] = g_S[(bh * 16 + c) * 16 + d] / (dq * dk) * temp;
    }
    float m = row[0];
#pragma unroll
    for (int d = 1; d < 16; d++) m = fmaxf(m, row[d]);
    float ex[16], sum = 0.f;
#pragma unroll
    for (int d = 0; d < 16; d++) { ex[d] = expf(row[d] - m); sum += ex[d]; }
    float inv = 1.f / sum;
    float a1[16];
#pragma unroll
    for (int d = 0; d < 16; d++) {
        float r = fmaxf(row[d], 0.f);
        float a = r * r;
        float g = a * 0.5f * (1.f + erff(a * 0.7071067811865476f));
        a1[d] = g * a;
    }
#pragma unroll
    for (int d = 0; d < 16; d++) {
        float sc = 0.f, sh = 0.f;
#pragma unroll
        for (int e = 0; e < 16; e++) {
            sc += attca_w[d * 16 + e] * a1[e];
            sh += attca_w[(16 + d) * 16 + e] * a1[e];
        }
        g_attnF[(bh * 16 + c) * 16 + d] = ex[d] * inv * (1.f + sc) + sh;
    }
}

// ------------------------------------------------------------------
// M[b][o][h*16+d] = sum_c proj_w[o][h*16+c] * attnF[b,h,c][d]
__global__ void proj_fold(const float* __restrict__ proj_w)
{
    int e  = blockIdx.x * 256 + threadIdx.x;   // 0..32767
    int b2 = e >> 14;
    int o  = (e >> 7) & 127;
    int jj = e & 127;
    int h2 = jj >> 4, d = jj & 15;
    float s = 0.f;
#pragma unroll
    for (int c2 = 0; c2 < 16; c2++)
        s += proj_w[o * 128 + h2 * 16 + c2] *
             g_attnF[((b2 * 8 + h2) * 16 + c2) * 16 + d];
    g_M[e] = s;
}

// ------------------------------------------------------------------
extern "C" void kernel_launch(void* const* d_in, const int* in_sizes, int n_in,
                              void* d_out, int out_size)
{
    const float* x           = (const float*)d_in[0];
    const float* qkv_w       = (const float*)d_in[1];
    const float* dw_w        = (const float*)d_in[2];
    const float* proj_w      = (const float*)d_in[3];
    const float* attca_w     = (const float*)d_in[4];
    const float* temperature = (const float*)d_in[5];
    float* out = (float*)d_out;

    float *p_qkv, *p_v, *p_M;
    __nv_bfloat16 *p_Whi, *p_Wlo, *p_Mhi, *p_Mlo;
    cudaGetSymbolAddress((void**)&p_qkv, g_qkv);
    cudaGetSymbolAddress((void**)&p_v,   g_v);
    cudaGetSymbolAddress((void**)&p_M,   g_M);
    cudaGetSymbolAddress((void**)&p_Whi, g_Whi);
    cudaGetSymbolAddress((void**)&p_Wlo, g_Wlo);
    cudaGetSymbolAddress((void**)&p_Mhi, g_Mhi);
    cudaGetSymbolAddress((void**)&p_Mlo, g_Mlo);

    cudaFuncSetAttribute(tc_gemm, cudaFuncAttributeMaxDynamicSharedMemorySize,
                         SM_BYTES);

    zero_acc<<<16, 256>>>();
    split_w<<<(384 * DIMC + 255) / 256, 256>>>(qkv_w, p_Whi, p_Wlo, 384 * DIMC);
    // qkv pointwise: [384x128] @ x[b][128][L]
    tc_gemm<<<dim3(L / (64 * TILES), 3, BATCH), 256, SM_BYTES>>>(
        p_Whi, p_Wlo, 0, x, (size_t)DIMC * L, p_qkv, (size_t)384 * L);
    // depthwise q/k + Gram reductions
    dw_qk_gram<<<dim3(IMG / 32, IMG / 8, BATCH * HEADS), 256>>>(dw_w);
    // depthwise v
    dw_v<<<dim3(IMG / 32, IMG / 8, BATCH * HEADS), 256>>>(dw_w);
    // attention math, then fold proj into M (parallel), then split M
    attn_small<<<1, 256>>>(attca_w, temperature);
    proj_fold<<<128, 256>>>(proj_w);
    split_w<<<(BATCH * DIMC * DIMC + 255) / 256, 256>>>(
        p_M, p_Mhi, p_Mlo, BATCH * DIMC * DIMC);
    // out = M_b @ v
    tc_gemm<<<dim3(L / (64 * TILES), 1, BATCH), 256, SM_BYTES>>>(
        p_Mhi, p_Mlo, (size_t)DIMC * DIMC, p_v, (size_t)DIMC * L,
        out, (size_t)DIMC * L);
}